// round 15
// baseline (speedup 1.0000x reference)
#include <cuda_runtime.h>
#include <cuda_fp16.h>
#include <math.h>
#include <cstdint>

#define BSZ 4096
#define ISZ 1024
#define HSZ 2048
#define NTH 256

// ---------------------------------------------------------------------------
// Device scratch: fp16 planes (weights kept in original [K,N] layout)
// ---------------------------------------------------------------------------
__device__ __half g_x16[BSZ * ISZ];
__device__ __half g_h16[BSZ * HSZ];
__device__ __half g_wgx[ISZ * HSZ];   // [K=I, N=H]
__device__ __half g_wgh[HSZ * HSZ];   // [K=H, N=H]
__device__ __half g_wxh[ISZ * HSZ];
__device__ __half g_whh[HSZ * HSZ];
__device__ __half g_linw[ISZ * HSZ];  // [N=I, K=H] (already B-layout)
__device__ __half g_hn16[BSZ * HSZ];

// ---------------------------------------------------------------------------
// PTX helpers (sm_80-era only: must compile for plain sm_103 target)
// ---------------------------------------------------------------------------
__device__ __forceinline__ uint32_t smem_u32(const void* p) {
    uint32_t a;
    asm("{ .reg .u64 t; cvta.to.shared.u64 t, %1; cvt.u32.u64 %0, t; }"
        : "=r"(a) : "l"(p));
    return a;
}

#define CP16(dst, src) \
    asm volatile("cp.async.cg.shared.global [%0], [%1], 16;" :: "r"(dst), "l"(src))
#define CP_COMMIT() asm volatile("cp.async.commit_group;" ::: "memory")
#define CP_WAITN(n) asm volatile("cp.async.wait_group %0;" :: "n"(n) : "memory")

#define LDMATRIX_X4(r0, r1, r2, r3, addr)                                   \
    asm volatile("ldmatrix.sync.aligned.m8n8.x4.shared.b16 {%0,%1,%2,%3}, [%4];" \
                 : "=r"(r0), "=r"(r1), "=r"(r2), "=r"(r3) : "r"(addr))

#define LDMATRIX_X4_T(r0, r1, r2, r3, addr)                                 \
    asm volatile("ldmatrix.sync.aligned.m8n8.x4.trans.shared.b16 {%0,%1,%2,%3}, [%4];" \
                 : "=r"(r0), "=r"(r1), "=r"(r2), "=r"(r3) : "r"(addr))

#define MMA16816(c, a, b0, b1)                                              \
    asm volatile("mma.sync.aligned.m16n8k16.row.col.f32.f16.f16.f32 "       \
                 "{%0,%1,%2,%3}, {%4,%5,%6,%7}, {%8,%9}, {%0,%1,%2,%3};"    \
                 : "+f"((c)[0]), "+f"((c)[1]), "+f"((c)[2]), "+f"((c)[3])   \
                 : "r"((a)[0]), "r"((a)[1]), "r"((a)[2]), "r"((a)[3]),      \
                   "r"(b0), "r"(b1))

// ---------------------------------------------------------------------------
// Prep: single fused fp32 -> fp16 convert (MLP=4, streaming stores)
// ---------------------------------------------------------------------------
#define NSEG 7
#define CONV_PER_THREAD 4
struct ConvSegs {
    const float4* src[NSEG];
    __half2*      dst[NSEG];
    int           n4[NSEG];
};

__global__ void conv_all_kernel(ConvSegs s) {
    const int base = blockIdx.x * (256 * CONV_PER_THREAD) + threadIdx.x;
#pragma unroll
    for (int j = 0; j < CONV_PER_THREAD; j++) {
        int i = base + j * 256;
#pragma unroll
        for (int t = 0; t < NSEG; t++) {
            if (i < s.n4[t]) {
                float4 v = s.src[t][i];
                uint32_t p0, p1;
                {
                    __half2 a = __halves2half2(__float2half_rn(v.x), __float2half_rn(v.y));
                    __half2 b = __halves2half2(__float2half_rn(v.z), __float2half_rn(v.w));
                    p0 = *reinterpret_cast<uint32_t*>(&a);
                    p1 = *reinterpret_cast<uint32_t*>(&b);
                }
                uint64_t packed = (uint64_t)p0 | ((uint64_t)p1 << 32);
                asm volatile("st.global.cs.u64 [%0], %1;"
                             :: "l"((uint64_t*)(s.dst[t] + 2 * i)), "l"(packed)
                             : "memory");
                break;
            }
            i -= s.n4[t];
        }
    }
}

// ---------------------------------------------------------------------------
// Tiling constants (BM=64, BN=128, BK=32; 8 warps, warp tile 32x32)
// 6 stages of 15360B; ONE barrier per chunk; wait <= 4 pending groups.
// ---------------------------------------------------------------------------
#define A_RSTRIDE 80                       // bytes per A smem row (32h + 8 pad)
#define A_BYTES (64 * A_RSTRIDE)           // 5120
#define BT_RSTRIDE 272                     // bytes per B k-row (128h + 8 pad)
#define BN_BYTES (128 * A_RSTRIDE)         // 10240 (covers BT: 32*272=8704)
#define STAGE_BYTES (A_BYTES + BN_BYTES)   // 15360
#define NSTAGE 6
#define SMEM_MAIN (NSTAGE * STAGE_BYTES)   // 92160 (x2 CTAs = 184320)

// steady-state: keep up to 4 older groups pending; taper at tail
#define PIPE_WAIT(c, n) do {                          \
    if ((c) + 1 >= (n))      { CP_WAITN(0); }         \
    else if ((c) + 2 >= (n)) { CP_WAITN(1); }         \
    else if ((c) + 3 >= (n)) { CP_WAITN(2); }         \
    else if ((c) + 4 >= (n)) { CP_WAITN(3); }         \
    else                     { CP_WAITN(4); }         \
} while (0)

// ---------------------------------------------------------------------------
// Merged gate GEMM: blockIdx.z = 0 -> g_new, 1 -> h_new. B via ldmatrix.trans.
// Single barrier per chunk. Stage written at iter c is (c+5)%6 = (c-1)%6,
// last read at iteration c-1, finished before this iteration's top barrier.
// ---------------------------------------------------------------------------
__global__ __launch_bounds__(NTH, 2) void gemm_gates_kernel(
    const float* __restrict__ b_g,
    const float* __restrict__ b_h,
    const float* __restrict__ graw,
    const float* __restrict__ hraw,
    float* __restrict__ g_new,
    float* __restrict__ h_new)
{
    extern __shared__ __align__(128) unsigned char dsm[];
    const uint32_t sb = smem_u32(dsm);
    const int tid = threadIdx.x;
    const int wid = tid >> 5, lane = tid & 31;
    const int rowBase = blockIdx.y * 64;
    const int colBase = blockIdx.x * 128;
    const int z = blockIdx.z;
    const int nchunks = (ISZ + HSZ) / 32;   // 96

    const int wm = (wid >> 2) * 32;
    const int wn = (wid & 3) * 32;

    float acc[2][4][4];
#pragma unroll
    for (int mi = 0; mi < 2; mi++)
#pragma unroll
        for (int ni = 0; ni < 4; ni++)
#pragma unroll
            for (int q = 0; q < 4; q++) acc[mi][ni][q] = 0.0f;

    auto load_chunk = [&](int c) {
        const int k0 = c * 32;
        const __half *A, *B;
        int lda, kk;
        if (k0 < ISZ) {
            A = g_x16; lda = ISZ; kk = k0;
            B = z ? g_wxh : g_wgx;
        } else {
            A = g_h16; lda = HSZ; kk = k0 - ISZ;
            B = z ? g_whh : g_wgh;
        }
        const uint32_t base = sb + (c % NSTAGE) * STAGE_BYTES;
        {
            const int row = tid >> 2, kc = tid & 3;
            CP16(base + row * A_RSTRIDE + kc * 16,
                 A + (size_t)(rowBase + row) * lda + kk + kc * 8);
        }
#pragma unroll
        for (int j = 0; j < 2; j++) {
            const int idx = tid * 2 + j;
            const int row = idx >> 4, nc = idx & 15;
            CP16(base + A_BYTES + row * BT_RSTRIDE + nc * 16,
                 B + (size_t)(kk + row) * HSZ + colBase + nc * 8);
        }
        CP_COMMIT();
    };

    load_chunk(0);
    load_chunk(1);
    load_chunk(2);
    load_chunk(3);
    load_chunk(4);

    for (int c = 0; c < nchunks; c++) {
        PIPE_WAIT(c, nchunks);
        __syncthreads();
        if (c + 5 < nchunks) load_chunk(c + 5);

        const uint32_t base = sb + (c % NSTAGE) * STAGE_BYTES;
        const uint32_t sA = base;
        const uint32_t sB = base + A_BYTES;

#pragma unroll
        for (int ks = 0; ks < 2; ks++) {
            const int k = ks * 16;
            const uint32_t aoff =
                (uint32_t)(wm + (lane & 15)) * A_RSTRIDE +
                (uint32_t)(k + ((lane >> 4) << 3)) * 2;
            uint32_t af[2][4];
#pragma unroll
            for (int mi = 0; mi < 2; mi++) {
                const uint32_t d = aoff + mi * 16 * A_RSTRIDE;
                LDMATRIX_X4(af[mi][0], af[mi][1], af[mi][2], af[mi][3], sA + d);
            }
            uint32_t bf[2][4];
            const int l8 = lane & 7, t8 = lane >> 3;
#pragma unroll
            for (int np = 0; np < 2; np++) {
                const uint32_t d =
                    (uint32_t)(k + (t8 & 1) * 8 + l8) * BT_RSTRIDE +
                    (uint32_t)(wn + np * 16 + (t8 >> 1) * 8) * 2;
                LDMATRIX_X4_T(bf[np][0], bf[np][1], bf[np][2], bf[np][3], sB + d);
            }
#pragma unroll
            for (int mi = 0; mi < 2; mi++)
#pragma unroll
                for (int ni = 0; ni < 4; ni++) {
                    const int np = ni >> 1, q = (ni & 1) * 2;
                    MMA16816(acc[mi][ni], af[mi], bf[np][q], bf[np][q + 1]);
                }
        }
    }

    const float* bias = z ? b_h : b_g;
    float* out = z ? h_new : g_new;

#pragma unroll
    for (int mi = 0; mi < 2; mi++) {
#pragma unroll
        for (int ni = 0; ni < 4; ni++) {
            const int col = colBase + wn + ni * 8 + (lane & 3) * 2;
#pragma unroll
            for (int hf = 0; hf < 2; hf++) {
                const int row = rowBase + wm + mi * 16 + (lane >> 2) + hf * 8;
                const float c0 = acc[mi][ni][hf * 2 + 0];
                const float c1 = acc[mi][ni][hf * 2 + 1];
                const size_t oidx = (size_t)row * HSZ + col;
                const float t0 = tanhf(c0 + bias[col]);
                const float t1 = tanhf(c1 + bias[col + 1]);
                if (z == 0) {
                    float2 r; r.x = t0; r.y = t1;
                    *(float2*)&out[oidx] = r;
                } else {
                    const float2 gv = *(const float2*)&graw[oidx];
                    const float2 hv = *(const float2*)&hraw[oidx];
                    float2 hn;
                    hn.x = gv.x * t0 + (1.0f - gv.x) * hv.x;
                    hn.y = gv.y * t1 + (1.0f - gv.y) * hv.y;
                    *(float2*)&out[oidx] = hn;
                    *(__half2*)&g_hn16[oidx] =
                        __halves2half2(__float2half_rn(hn.x), __float2half_rn(hn.y));
                }
            }
        }
    }
}

// ---------------------------------------------------------------------------
// Output GEMM: o = h_new @ lin_w^T + lin_b (B is [N,K], non-trans path)
// ---------------------------------------------------------------------------
__global__ __launch_bounds__(NTH, 2) void gemm_out_kernel(
    const float* __restrict__ bias,
    float* __restrict__ out)
{
    extern __shared__ __align__(128) unsigned char dsm[];
    const uint32_t sb = smem_u32(dsm);
    const int tid = threadIdx.x;
    const int wid = tid >> 5, lane = tid & 31;
    const int rowBase = blockIdx.y * 64;
    const int colBase = blockIdx.x * 128;
    const int nchunks = HSZ / 32;   // 64

    const int wm = (wid >> 2) * 32;
    const int wn = (wid & 3) * 32;

    float acc[2][4][4];
#pragma unroll
    for (int mi = 0; mi < 2; mi++)
#pragma unroll
        for (int ni = 0; ni < 4; ni++)
#pragma unroll
            for (int q = 0; q < 4; q++) acc[mi][ni][q] = 0.0f;

    auto load_chunk = [&](int c) {
        const int kk = c * 32;
        const uint32_t base = sb + (c % NSTAGE) * STAGE_BYTES;
        {
            const int row = tid >> 2, kc = tid & 3;
            CP16(base + row * A_RSTRIDE + kc * 16,
                 g_hn16 + (size_t)(rowBase + row) * HSZ + kk + kc * 8);
        }
#pragma unroll
        for (int j = 0; j < 2; j++) {
            const int idx = tid * 2 + j;
            const int row = idx >> 2, kc = idx & 3;
            CP16(base + A_BYTES + row * A_RSTRIDE + kc * 16,
                 g_linw + (size_t)(colBase + row) * HSZ + kk + kc * 8);
        }
        CP_COMMIT();
    };

    load_chunk(0);
    load_chunk(1);
    load_chunk(2);
    load_chunk(3);
    load_chunk(4);

    for (int c = 0; c < nchunks; c++) {
        PIPE_WAIT(c, nchunks);
        __syncthreads();
        if (c + 5 < nchunks) load_chunk(c + 5);

        const uint32_t base = sb + (c % NSTAGE) * STAGE_BYTES;
        const uint32_t sA = base;
        const uint32_t sB = base + A_BYTES;

#pragma unroll
        for (int ks = 0; ks < 2; ks++) {
            const int k = ks * 16;
            const uint32_t aoff =
                (uint32_t)(wm + (lane & 15)) * A_RSTRIDE +
                (uint32_t)(k + ((lane >> 4) << 3)) * 2;
            uint32_t af[2][4];
#pragma unroll
            for (int mi = 0; mi < 2; mi++) {
                const uint32_t d = aoff + mi * 16 * A_RSTRIDE;
                LDMATRIX_X4(af[mi][0], af[mi][1], af[mi][2], af[mi][3], sA + d);
            }
            const uint32_t boff =
                (uint32_t)(wn + ((lane >> 4) << 3) + (lane & 7)) * A_RSTRIDE +
                (uint32_t)(k + (((lane >> 3) & 1) << 3)) * 2;
            uint32_t bf[2][4];
#pragma unroll
            for (int np = 0; np < 2; np++) {
                const uint32_t d = boff + np * 16 * A_RSTRIDE;
                LDMATRIX_X4(bf[np][0], bf[np][1], bf[np][2], bf[np][3], sB + d);
            }
#pragma unroll
            for (int mi = 0; mi < 2; mi++)
#pragma unroll
                for (int ni = 0; ni < 4; ni++) {
                    const int np = ni >> 1, q = (ni & 1) * 2;
                    MMA16816(acc[mi][ni], af[mi], bf[np][q], bf[np][q + 1]);
                }
        }
    }

#pragma unroll
    for (int mi = 0; mi < 2; mi++) {
#pragma unroll
        for (int ni = 0; ni < 4; ni++) {
            const int col = colBase + wn + ni * 8 + (lane & 3) * 2;
#pragma unroll
            for (int hf = 0; hf < 2; hf++) {
                const int row = rowBase + wm + mi * 16 + (lane >> 2) + hf * 8;
                float2 r;
                r.x = acc[mi][ni][hf * 2 + 0] + bias[col];
                r.y = acc[mi][ni][hf * 2 + 1] + bias[col + 1];
                *(float2*)&out[(size_t)row * ISZ + col] = r;
            }
        }
    }
}

// ---------------------------------------------------------------------------
// Launch
// ---------------------------------------------------------------------------
extern "C" void kernel_launch(void* const* d_in, const int* in_sizes, int n_in,
                              void* d_out, int out_size) {
    const float* x     = (const float*)d_in[0];
    const float* h     = (const float*)d_in[1];
    const float* g     = (const float*)d_in[2];
    const float* w_xh  = (const float*)d_in[3];
    const float* w_hh  = (const float*)d_in[4];
    const float* b_h   = (const float*)d_in[5];
    const float* w_gx  = (const float*)d_in[6];
    const float* w_gh  = (const float*)d_in[7];
    const float* b_g   = (const float*)d_in[8];
    const float* lin_w = (const float*)d_in[9];
    const float* lin_b = (const float*)d_in[10];

    float* o     = (float*)d_out;
    float* h_new = o + (size_t)BSZ * ISZ;
    float* g_new = h_new + (size_t)BSZ * HSZ;

    void *x16, *h16, *lw, *gx, *gh, *xh, *hh;
    cudaGetSymbolAddress(&x16, g_x16);
    cudaGetSymbolAddress(&h16, g_h16);
    cudaGetSymbolAddress(&lw, g_linw);
    cudaGetSymbolAddress(&gx, g_wgx);
    cudaGetSymbolAddress(&gh, g_wgh);
    cudaGetSymbolAddress(&xh, g_wxh);
    cudaGetSymbolAddress(&hh, g_whh);

    cudaFuncSetAttribute(gemm_gates_kernel, cudaFuncAttributeMaxDynamicSharedMemorySize, SMEM_MAIN);
    cudaFuncSetAttribute(gemm_out_kernel,   cudaFuncAttributeMaxDynamicSharedMemorySize, SMEM_MAIN);

    // single fused fp32 -> fp16 convert (MLP=4, streaming stores)
    ConvSegs segs;
    segs.src[0] = (const float4*)x;     segs.dst[0] = (__half2*)x16; segs.n4[0] = BSZ * ISZ / 4;
    segs.src[1] = (const float4*)h;     segs.dst[1] = (__half2*)h16; segs.n4[1] = BSZ * HSZ / 4;
    segs.src[2] = (const float4*)lin_w; segs.dst[2] = (__half2*)lw;  segs.n4[2] = ISZ * HSZ / 4;
    segs.src[3] = (const float4*)w_gx;  segs.dst[3] = (__half2*)gx;  segs.n4[3] = ISZ * HSZ / 4;
    segs.src[4] = (const float4*)w_gh;  segs.dst[4] = (__half2*)gh;  segs.n4[4] = HSZ * HSZ / 4;
    segs.src[5] = (const float4*)w_xh;  segs.dst[5] = (__half2*)xh;  segs.n4[5] = ISZ * HSZ / 4;
    segs.src[6] = (const float4*)w_hh;  segs.dst[6] = (__half2*)hh;  segs.n4[6] = HSZ * HSZ / 4;
    int total4 = 0;
    for (int t = 0; t < NSEG; t++) total4 += segs.n4[t];
    const int conv_blocks = (total4 + 256 * CONV_PER_THREAD - 1) / (256 * CONV_PER_THREAD);
    conv_all_kernel<<<conv_blocks, 256>>>(segs);

    // merged gate GEMMs (z=0: g_new, z=1: h_new)
    gemm_gates_kernel<<<dim3(HSZ / 128, BSZ / 64, 2), NTH, SMEM_MAIN>>>(
        b_g, b_h, g, h, g_new, h_new);

    // output GEMM
    gemm_out_kernel<<<dim3(ISZ / 128, BSZ / 64), NTH, SMEM_MAIN>>>(lin_b, o);
}

// round 16
// speedup vs baseline: 1.0189x; 1.0189x over previous
#include <cuda_runtime.h>
#include <cuda_fp16.h>
#include <math.h>
#include <cstdint>

#define BSZ 4096
#define ISZ 1024
#define HSZ 2048
#define NTH 256

// ---------------------------------------------------------------------------
// Device scratch: fp16 planes (weights kept in original [K,N] layout)
// ---------------------------------------------------------------------------
__device__ __half g_x16[BSZ * ISZ];
__device__ __half g_h16[BSZ * HSZ];
__device__ __half g_wgx[ISZ * HSZ];   // [K=I, N=H]
__device__ __half g_wgh[HSZ * HSZ];   // [K=H, N=H]
__device__ __half g_wxh[ISZ * HSZ];
__device__ __half g_whh[HSZ * HSZ];
__device__ __half g_linw[ISZ * HSZ];  // [N=I, K=H] (already B-layout)
__device__ __half g_hn16[BSZ * HSZ];

// ---------------------------------------------------------------------------
// PTX helpers (sm_80-era only: must compile for plain sm_103 target)
// ---------------------------------------------------------------------------
__device__ __forceinline__ uint32_t smem_u32(const void* p) {
    uint32_t a;
    asm("{ .reg .u64 t; cvta.to.shared.u64 t, %1; cvt.u32.u64 %0, t; }"
        : "=r"(a) : "l"(p));
    return a;
}

#define CP16(dst, src) \
    asm volatile("cp.async.cg.shared.global [%0], [%1], 16;" :: "r"(dst), "l"(src))
#define CP_COMMIT() asm volatile("cp.async.commit_group;" ::: "memory")
#define CP_WAITN(n) asm volatile("cp.async.wait_group %0;" :: "n"(n) : "memory")

#define LDMATRIX_X4(r0, r1, r2, r3, addr)                                   \
    asm volatile("ldmatrix.sync.aligned.m8n8.x4.shared.b16 {%0,%1,%2,%3}, [%4];" \
                 : "=r"(r0), "=r"(r1), "=r"(r2), "=r"(r3) : "r"(addr))

#define LDMATRIX_X4_T(r0, r1, r2, r3, addr)                                 \
    asm volatile("ldmatrix.sync.aligned.m8n8.x4.trans.shared.b16 {%0,%1,%2,%3}, [%4];" \
                 : "=r"(r0), "=r"(r1), "=r"(r2), "=r"(r3) : "r"(addr))

#define MMA16816(c, a, b0, b1)                                              \
    asm volatile("mma.sync.aligned.m16n8k16.row.col.f32.f16.f16.f32 "       \
                 "{%0,%1,%2,%3}, {%4,%5,%6,%7}, {%8,%9}, {%0,%1,%2,%3};"    \
                 : "+f"((c)[0]), "+f"((c)[1]), "+f"((c)[2]), "+f"((c)[3])   \
                 : "r"((a)[0]), "r"((a)[1]), "r"((a)[2]), "r"((a)[3]),      \
                   "r"(b0), "r"(b1))

// ---------------------------------------------------------------------------
// Prep: single fused fp32 -> fp16 convert (MLP=4, streaming stores)
// ---------------------------------------------------------------------------
#define NSEG 7
#define CONV_PER_THREAD 4
struct ConvSegs {
    const float4* src[NSEG];
    __half2*      dst[NSEG];
    int           n4[NSEG];
};

__global__ void conv_all_kernel(ConvSegs s) {
    const int base = blockIdx.x * (256 * CONV_PER_THREAD) + threadIdx.x;
#pragma unroll
    for (int j = 0; j < CONV_PER_THREAD; j++) {
        int i = base + j * 256;
#pragma unroll
        for (int t = 0; t < NSEG; t++) {
            if (i < s.n4[t]) {
                float4 v = s.src[t][i];
                uint32_t p0, p1;
                {
                    __half2 a = __halves2half2(__float2half_rn(v.x), __float2half_rn(v.y));
                    __half2 b = __halves2half2(__float2half_rn(v.z), __float2half_rn(v.w));
                    p0 = *reinterpret_cast<uint32_t*>(&a);
                    p1 = *reinterpret_cast<uint32_t*>(&b);
                }
                uint64_t packed = (uint64_t)p0 | ((uint64_t)p1 << 32);
                asm volatile("st.global.cs.u64 [%0], %1;"
                             :: "l"((uint64_t*)(s.dst[t] + 2 * i)), "l"(packed)
                             : "memory");
                break;
            }
            i -= s.n4[t];
        }
    }
}

// ---------------------------------------------------------------------------
// Tiling constants (BM=64, BN=128, BK=32; 8 warps, warp tile 32x32)
// 5 stages of 15360B; one barrier per chunk; wait <= 3 pending groups.
// ---------------------------------------------------------------------------
#define A_RSTRIDE 80                       // bytes per A smem row (32h + 8 pad)
#define A_BYTES (64 * A_RSTRIDE)           // 5120
#define BT_RSTRIDE 272                     // bytes per B k-row (128h + 8 pad)
#define BN_BYTES (128 * A_RSTRIDE)         // 10240 (covers BT: 32*272=8704)
#define STAGE_BYTES (A_BYTES + BN_BYTES)   // 15360
#define NSTAGE 5
#define SMEM_MAIN (NSTAGE * STAGE_BYTES)   // 76800 (x2 CTAs = 153600)

// tail-only tapered wait
#define PIPE_WAIT_TAIL(c, n) do {                     \
    if ((c) + 1 >= (n))      { CP_WAITN(0); }         \
    else if ((c) + 2 >= (n)) { CP_WAITN(1); }         \
    else if ((c) + 3 >= (n)) { CP_WAITN(2); }         \
    else                     { CP_WAITN(3); }         \
} while (0)

// ---------------------------------------------------------------------------
// Merged gate GEMM: blockIdx.z = 0 -> g_new, 1 -> h_new. B via ldmatrix.trans.
// Single barrier per chunk. Stage written at iter c is (c+4)%5 = (c-1)%5,
// last read at iteration c-1, finished before this iteration's top barrier.
// Steady-state loop has constant wait (branch-free); 4-iter tapered tail.
// ---------------------------------------------------------------------------
__global__ __launch_bounds__(NTH, 2) void gemm_gates_kernel(
    const float* __restrict__ b_g,
    const float* __restrict__ b_h,
    const float* __restrict__ graw,
    const float* __restrict__ hraw,
    float* __restrict__ g_new,
    float* __restrict__ h_new)
{
    extern __shared__ __align__(128) unsigned char dsm[];
    const uint32_t sb = smem_u32(dsm);
    const int tid = threadIdx.x;
    const int wid = tid >> 5, lane = tid & 31;
    const int rowBase = blockIdx.y * 64;
    const int colBase = blockIdx.x * 128;
    const int z = blockIdx.z;
    const int nchunks = (ISZ + HSZ) / 32;   // 96

    const int wm = (wid >> 2) * 32;
    const int wn = (wid & 3) * 32;

    float acc[2][4][4];
#pragma unroll
    for (int mi = 0; mi < 2; mi++)
#pragma unroll
        for (int ni = 0; ni < 4; ni++)
#pragma unroll
            for (int q = 0; q < 4; q++) acc[mi][ni][q] = 0.0f;

    auto load_chunk = [&](int c) {
        const int k0 = c * 32;
        const __half *A, *B;
        int lda, kk;
        if (k0 < ISZ) {
            A = g_x16; lda = ISZ; kk = k0;
            B = z ? g_wxh : g_wgx;
        } else {
            A = g_h16; lda = HSZ; kk = k0 - ISZ;
            B = z ? g_whh : g_wgh;
        }
        const uint32_t base = sb + (c % NSTAGE) * STAGE_BYTES;
        {
            const int row = tid >> 2, kc = tid & 3;
            CP16(base + row * A_RSTRIDE + kc * 16,
                 A + (size_t)(rowBase + row) * lda + kk + kc * 8);
        }
#pragma unroll
        for (int j = 0; j < 2; j++) {
            const int idx = tid * 2 + j;
            const int row = idx >> 4, nc = idx & 15;
            CP16(base + A_BYTES + row * BT_RSTRIDE + nc * 16,
                 B + (size_t)(kk + row) * HSZ + colBase + nc * 8);
        }
        CP_COMMIT();
    };

    auto compute_chunk = [&](int c) {
        const uint32_t base = sb + (c % NSTAGE) * STAGE_BYTES;
        const uint32_t sA = base;
        const uint32_t sB = base + A_BYTES;
#pragma unroll
        for (int ks = 0; ks < 2; ks++) {
            const int k = ks * 16;
            const uint32_t aoff =
                (uint32_t)(wm + (lane & 15)) * A_RSTRIDE +
                (uint32_t)(k + ((lane >> 4) << 3)) * 2;
            uint32_t af[2][4];
#pragma unroll
            for (int mi = 0; mi < 2; mi++) {
                const uint32_t d = aoff + mi * 16 * A_RSTRIDE;
                LDMATRIX_X4(af[mi][0], af[mi][1], af[mi][2], af[mi][3], sA + d);
            }
            uint32_t bf[2][4];
            const int l8 = lane & 7, t8 = lane >> 3;
#pragma unroll
            for (int np = 0; np < 2; np++) {
                const uint32_t d =
                    (uint32_t)(k + (t8 & 1) * 8 + l8) * BT_RSTRIDE +
                    (uint32_t)(wn + np * 16 + (t8 >> 1) * 8) * 2;
                LDMATRIX_X4_T(bf[np][0], bf[np][1], bf[np][2], bf[np][3], sB + d);
            }
#pragma unroll
            for (int mi = 0; mi < 2; mi++)
#pragma unroll
                for (int ni = 0; ni < 4; ni++) {
                    const int np = ni >> 1, q = (ni & 1) * 2;
                    MMA16816(acc[mi][ni], af[mi], bf[np][q], bf[np][q + 1]);
                }
        }
    };

    load_chunk(0);
    load_chunk(1);
    load_chunk(2);
    load_chunk(3);

    int c = 0;
    for (; c + 4 < nchunks; c++) {      // steady state: constant wait
        CP_WAITN(3);
        __syncthreads();
        load_chunk(c + 4);
        compute_chunk(c);
    }
    for (; c < nchunks; c++) {          // 4-iteration tapered tail
        PIPE_WAIT_TAIL(c, nchunks);
        __syncthreads();
        compute_chunk(c);
    }

    const float* bias = z ? b_h : b_g;
    float* out = z ? h_new : g_new;

#pragma unroll
    for (int mi = 0; mi < 2; mi++) {
#pragma unroll
        for (int ni = 0; ni < 4; ni++) {
            const int col = colBase + wn + ni * 8 + (lane & 3) * 2;
#pragma unroll
            for (int hf = 0; hf < 2; hf++) {
                const int row = rowBase + wm + mi * 16 + (lane >> 2) + hf * 8;
                const float c0 = acc[mi][ni][hf * 2 + 0];
                const float c1 = acc[mi][ni][hf * 2 + 1];
                const size_t oidx = (size_t)row * HSZ + col;
                const float t0 = tanhf(c0 + bias[col]);
                const float t1 = tanhf(c1 + bias[col + 1]);
                if (z == 0) {
                    float2 r; r.x = t0; r.y = t1;
                    *(float2*)&out[oidx] = r;
                } else {
                    const float2 gv = *(const float2*)&graw[oidx];
                    const float2 hv = *(const float2*)&hraw[oidx];
                    float2 hn;
                    hn.x = gv.x * t0 + (1.0f - gv.x) * hv.x;
                    hn.y = gv.y * t1 + (1.0f - gv.y) * hv.y;
                    *(float2*)&out[oidx] = hn;
                    *(__half2*)&g_hn16[oidx] =
                        __halves2half2(__float2half_rn(hn.x), __float2half_rn(hn.y));
                }
            }
        }
    }
}

// ---------------------------------------------------------------------------
// Output GEMM: o = h_new @ lin_w^T + lin_b (B is [N,K], non-trans path)
// ---------------------------------------------------------------------------
__global__ __launch_bounds__(NTH, 2) void gemm_out_kernel(
    const float* __restrict__ bias,
    float* __restrict__ out)
{
    extern __shared__ __align__(128) unsigned char dsm[];
    const uint32_t sb = smem_u32(dsm);
    const int tid = threadIdx.x;
    const int wid = tid >> 5, lane = tid & 31;
    const int rowBase = blockIdx.y * 64;
    const int colBase = blockIdx.x * 128;
    const int nchunks = HSZ / 32;   // 64

    const int wm = (wid >> 2) * 32;
    const int wn = (wid & 3) * 32;

    float acc[2][4][4];
#pragma unroll
    for (int mi = 0; mi < 2; mi++)
#pragma unroll
        for (int ni = 0; ni < 4; ni++)
#pragma unroll
            for (int q = 0; q < 4; q++) acc[mi][ni][q] = 0.0f;

    auto load_chunk = [&](int c) {
        const int kk = c * 32;
        const uint32_t base = sb + (c % NSTAGE) * STAGE_BYTES;
        {
            const int row = tid >> 2, kc = tid & 3;
            CP16(base + row * A_RSTRIDE + kc * 16,
                 g_hn16 + (size_t)(rowBase + row) * HSZ + kk + kc * 8);
        }
#pragma unroll
        for (int j = 0; j < 2; j++) {
            const int idx = tid * 2 + j;
            const int row = idx >> 2, kc = idx & 3;
            CP16(base + A_BYTES + row * A_RSTRIDE + kc * 16,
                 g_linw + (size_t)(colBase + row) * HSZ + kk + kc * 8);
        }
        CP_COMMIT();
    };

    auto compute_chunk = [&](int c) {
        const uint32_t base = sb + (c % NSTAGE) * STAGE_BYTES;
        const uint32_t sA = base;
        const uint32_t sB = base + A_BYTES;
#pragma unroll
        for (int ks = 0; ks < 2; ks++) {
            const int k = ks * 16;
            const uint32_t aoff =
                (uint32_t)(wm + (lane & 15)) * A_RSTRIDE +
                (uint32_t)(k + ((lane >> 4) << 3)) * 2;
            uint32_t af[2][4];
#pragma unroll
            for (int mi = 0; mi < 2; mi++) {
                const uint32_t d = aoff + mi * 16 * A_RSTRIDE;
                LDMATRIX_X4(af[mi][0], af[mi][1], af[mi][2], af[mi][3], sA + d);
            }
            const uint32_t boff =
                (uint32_t)(wn + ((lane >> 4) << 3) + (lane & 7)) * A_RSTRIDE +
                (uint32_t)(k + (((lane >> 3) & 1) << 3)) * 2;
            uint32_t bf[2][4];
#pragma unroll
            for (int np = 0; np < 2; np++) {
                const uint32_t d = boff + np * 16 * A_RSTRIDE;
                LDMATRIX_X4(bf[np][0], bf[np][1], bf[np][2], bf[np][3], sB + d);
            }
#pragma unroll
            for (int mi = 0; mi < 2; mi++)
#pragma unroll
                for (int ni = 0; ni < 4; ni++) {
                    const int np = ni >> 1, q = (ni & 1) * 2;
                    MMA16816(acc[mi][ni], af[mi], bf[np][q], bf[np][q + 1]);
                }
        }
    };

    load_chunk(0);
    load_chunk(1);
    load_chunk(2);
    load_chunk(3);

    int c = 0;
    for (; c + 4 < nchunks; c++) {      // steady state: constant wait
        CP_WAITN(3);
        __syncthreads();
        load_chunk(c + 4);
        compute_chunk(c);
    }
    for (; c < nchunks; c++) {          // tapered tail
        PIPE_WAIT_TAIL(c, nchunks);
        __syncthreads();
        compute_chunk(c);
    }

#pragma unroll
    for (int mi = 0; mi < 2; mi++) {
#pragma unroll
        for (int ni = 0; ni < 4; ni++) {
            const int col = colBase + wn + ni * 8 + (lane & 3) * 2;
#pragma unroll
            for (int hf = 0; hf < 2; hf++) {
                const int row = rowBase + wm + mi * 16 + (lane >> 2) + hf * 8;
                float2 r;
                r.x = acc[mi][ni][hf * 2 + 0] + bias[col];
                r.y = acc[mi][ni][hf * 2 + 1] + bias[col + 1];
                *(float2*)&out[(size_t)row * ISZ + col] = r;
            }
        }
    }
}

// ---------------------------------------------------------------------------
// Launch
// ---------------------------------------------------------------------------
extern "C" void kernel_launch(void* const* d_in, const int* in_sizes, int n_in,
                              void* d_out, int out_size) {
    const float* x     = (const float*)d_in[0];
    const float* h     = (const float*)d_in[1];
    const float* g     = (const float*)d_in[2];
    const float* w_xh  = (const float*)d_in[3];
    const float* w_hh  = (const float*)d_in[4];
    const float* b_h   = (const float*)d_in[5];
    const float* w_gx  = (const float*)d_in[6];
    const float* w_gh  = (const float*)d_in[7];
    const float* b_g   = (const float*)d_in[8];
    const float* lin_w = (const float*)d_in[9];
    const float* lin_b = (const float*)d_in[10];

    float* o     = (float*)d_out;
    float* h_new = o + (size_t)BSZ * ISZ;
    float* g_new = h_new + (size_t)BSZ * HSZ;

    void *x16, *h16, *lw, *gx, *gh, *xh, *hh;
    cudaGetSymbolAddress(&x16, g_x16);
    cudaGetSymbolAddress(&h16, g_h16);
    cudaGetSymbolAddress(&lw, g_linw);
    cudaGetSymbolAddress(&gx, g_wgx);
    cudaGetSymbolAddress(&gh, g_wgh);
    cudaGetSymbolAddress(&xh, g_wxh);
    cudaGetSymbolAddress(&hh, g_whh);

    cudaFuncSetAttribute(gemm_gates_kernel, cudaFuncAttributeMaxDynamicSharedMemorySize, SMEM_MAIN);
    cudaFuncSetAttribute(gemm_out_kernel,   cudaFuncAttributeMaxDynamicSharedMemorySize, SMEM_MAIN);

    // single fused fp32 -> fp16 convert (MLP=4, streaming stores)
    ConvSegs segs;
    segs.src[0] = (const float4*)x;     segs.dst[0] = (__half2*)x16; segs.n4[0] = BSZ * ISZ / 4;
    segs.src[1] = (const float4*)h;     segs.dst[1] = (__half2*)h16; segs.n4[1] = BSZ * HSZ / 4;
    segs.src[2] = (const float4*)lin_w; segs.dst[2] = (__half2*)lw;  segs.n4[2] = ISZ * HSZ / 4;
    segs.src[3] = (const float4*)w_gx;  segs.dst[3] = (__half2*)gx;  segs.n4[3] = ISZ * HSZ / 4;
    segs.src[4] = (const float4*)w_gh;  segs.dst[4] = (__half2*)gh;  segs.n4[4] = HSZ * HSZ / 4;
    segs.src[5] = (const float4*)w_xh;  segs.dst[5] = (__half2*)xh;  segs.n4[5] = ISZ * HSZ / 4;
    segs.src[6] = (const float4*)w_hh;  segs.dst[6] = (__half2*)hh;  segs.n4[6] = HSZ * HSZ / 4;
    int total4 = 0;
    for (int t = 0; t < NSEG; t++) total4 += segs.n4[t];
    const int conv_blocks = (total4 + 256 * CONV_PER_THREAD - 1) / (256 * CONV_PER_THREAD);
    conv_all_kernel<<<conv_blocks, 256>>>(segs);

    // merged gate GEMMs (z=0: g_new, z=1: h_new)
    gemm_gates_kernel<<<dim3(HSZ / 128, BSZ / 64, 2), NTH, SMEM_MAIN>>>(
        b_g, b_h, g, h, g_new, h_new);

    // output GEMM
    gemm_out_kernel<<<dim3(ISZ / 128, BSZ / 64), NTH, SMEM_MAIN>>>(lin_b, o);
}

// round 17
// speedup vs baseline: 1.1066x; 1.0860x over previous
#include <cuda_runtime.h>
#include <cuda_fp16.h>
#include <math.h>
#include <cstdint>

#define BSZ 4096
#define ISZ 1024
#define HSZ 2048
#define NTH 256

// ---------------------------------------------------------------------------
// Device scratch: fp16 planes (weights kept in original [K,N] layout)
// ---------------------------------------------------------------------------
__device__ __half g_x16[BSZ * ISZ];
__device__ __half g_h16[BSZ * HSZ];
__device__ __half g_wgx[ISZ * HSZ];   // [K=I, N=H]
__device__ __half g_wgh[HSZ * HSZ];   // [K=H, N=H]
__device__ __half g_wxh[ISZ * HSZ];
__device__ __half g_whh[HSZ * HSZ];
__device__ __half g_linw[ISZ * HSZ];  // [N=I, K=H] (already B-layout)
__device__ __half g_hn16[BSZ * HSZ];

// ---------------------------------------------------------------------------
// PTX helpers (sm_80-era only: must compile for plain sm_103 target)
// ---------------------------------------------------------------------------
__device__ __forceinline__ uint32_t smem_u32(const void* p) {
    uint32_t a;
    asm("{ .reg .u64 t; cvta.to.shared.u64 t, %1; cvt.u32.u64 %0, t; }"
        : "=r"(a) : "l"(p));
    return a;
}

#define CP16(dst, src) \
    asm volatile("cp.async.cg.shared.global [%0], [%1], 16;" :: "r"(dst), "l"(src))
#define CP_COMMIT() asm volatile("cp.async.commit_group;" ::: "memory")
#define CP_WAITN(n) asm volatile("cp.async.wait_group %0;" :: "n"(n) : "memory")

#define LDMATRIX_X4(r0, r1, r2, r3, addr)                                   \
    asm volatile("ldmatrix.sync.aligned.m8n8.x4.shared.b16 {%0,%1,%2,%3}, [%4];" \
                 : "=r"(r0), "=r"(r1), "=r"(r2), "=r"(r3) : "r"(addr))

#define LDMATRIX_X4_T(r0, r1, r2, r3, addr)                                 \
    asm volatile("ldmatrix.sync.aligned.m8n8.x4.trans.shared.b16 {%0,%1,%2,%3}, [%4];" \
                 : "=r"(r0), "=r"(r1), "=r"(r2), "=r"(r3) : "r"(addr))

#define MMA16816(c, a, b0, b1)                                              \
    asm volatile("mma.sync.aligned.m16n8k16.row.col.f32.f16.f16.f32 "       \
                 "{%0,%1,%2,%3}, {%4,%5,%6,%7}, {%8,%9}, {%0,%1,%2,%3};"    \
                 : "+f"((c)[0]), "+f"((c)[1]), "+f"((c)[2]), "+f"((c)[3])   \
                 : "r"((a)[0]), "r"((a)[1]), "r"((a)[2]), "r"((a)[3]),      \
                   "r"(b0), "r"(b1))

// ---------------------------------------------------------------------------
// Prep: single fused fp32 -> fp16 convert (MLP=4, streaming stores)
// ---------------------------------------------------------------------------
#define NSEG 7
#define CONV_PER_THREAD 4
struct ConvSegs {
    const float4* src[NSEG];
    __half2*      dst[NSEG];
    int           n4[NSEG];
};

__global__ void conv_all_kernel(ConvSegs s) {
    const int base = blockIdx.x * (256 * CONV_PER_THREAD) + threadIdx.x;
#pragma unroll
    for (int j = 0; j < CONV_PER_THREAD; j++) {
        int i = base + j * 256;
#pragma unroll
        for (int t = 0; t < NSEG; t++) {
            if (i < s.n4[t]) {
                float4 v = s.src[t][i];
                uint32_t p0, p1;
                {
                    __half2 a = __halves2half2(__float2half_rn(v.x), __float2half_rn(v.y));
                    __half2 b = __halves2half2(__float2half_rn(v.z), __float2half_rn(v.w));
                    p0 = *reinterpret_cast<uint32_t*>(&a);
                    p1 = *reinterpret_cast<uint32_t*>(&b);
                }
                uint64_t packed = (uint64_t)p0 | ((uint64_t)p1 << 32);
                asm volatile("st.global.cs.u64 [%0], %1;"
                             :: "l"((uint64_t*)(s.dst[t] + 2 * i)), "l"(packed)
                             : "memory");
                break;
            }
            i -= s.n4[t];
        }
    }
}

// ---------------------------------------------------------------------------
// Tiling constants (BM=64, BN=128, BK=32; 8 warps, warp tile 32x32)
// 5 stages of 15360B; one barrier per chunk; wait <= 3 pending groups.
// Steady loop unrolled by 5: stage indices are compile-time constants.
// ---------------------------------------------------------------------------
#define A_RSTRIDE 80                       // bytes per A smem row (32h + 8 pad)
#define A_BYTES (64 * A_RSTRIDE)           // 5120
#define BT_RSTRIDE 272                     // bytes per B k-row (128h + 8 pad)
#define BN_BYTES (128 * A_RSTRIDE)         // 10240 (covers BT: 32*272=8704)
#define STAGE_BYTES (A_BYTES + BN_BYTES)   // 15360
#define NSTAGE 5
#define SMEM_MAIN (NSTAGE * STAGE_BYTES)   // 76800 (x2 CTAs = 153600)

// tail-only tapered wait
#define PIPE_WAIT_TAIL(c, n) do {                     \
    if ((c) + 1 >= (n))      { CP_WAITN(0); }         \
    else if ((c) + 2 >= (n)) { CP_WAITN(1); }         \
    else if ((c) + 3 >= (n)) { CP_WAITN(2); }         \
    else                     { CP_WAITN(3); }         \
} while (0)

// ---------------------------------------------------------------------------
// Merged gate GEMM: blockIdx.z = 0 -> g_new, 1 -> h_new. B via ldmatrix.trans.
// Single barrier per chunk. Stage written at iter c is (c+4)%5 = (c-1)%5.
// ---------------------------------------------------------------------------
__global__ __launch_bounds__(NTH, 2) void gemm_gates_kernel(
    const float* __restrict__ b_g,
    const float* __restrict__ b_h,
    const float* __restrict__ graw,
    const float* __restrict__ hraw,
    float* __restrict__ g_new,
    float* __restrict__ h_new)
{
    extern __shared__ __align__(128) unsigned char dsm[];
    const uint32_t sb = smem_u32(dsm);
    const int tid = threadIdx.x;
    const int wid = tid >> 5, lane = tid & 31;
    const int rowBase = blockIdx.y * 64;
    const int colBase = blockIdx.x * 128;
    const int z = blockIdx.z;
    const int nchunks = (ISZ + HSZ) / 32;   // 96

    const int wm = (wid >> 2) * 32;
    const int wn = (wid & 3) * 32;

    // hoisted pointer selection + per-thread loader offsets
    const __half* Bx = z ? g_wxh : g_wgx;   // [ISZ, HSZ]
    const __half* Bh = z ? g_whh : g_wgh;   // [HSZ, HSZ]
    const int aRow = tid >> 2, aKc = tid & 3;
    const uint32_t aSoff = (uint32_t)aRow * A_RSTRIDE + aKc * 16;
    const int bRow0 = (tid * 2) >> 4, bNc0 = (tid * 2) & 15;
    const int bRow1 = (tid * 2 + 1) >> 4, bNc1 = (tid * 2 + 1) & 15;
    const uint32_t bSoff0 = (uint32_t)bRow0 * BT_RSTRIDE + bNc0 * 16;
    const uint32_t bSoff1 = (uint32_t)bRow1 * BT_RSTRIDE + bNc1 * 16;

    float acc[2][4][4];
#pragma unroll
    for (int mi = 0; mi < 2; mi++)
#pragma unroll
        for (int ni = 0; ni < 4; ni++)
#pragma unroll
            for (int q = 0; q < 4; q++) acc[mi][ni][q] = 0.0f;

    auto load_chunk_s = [&](int c, uint32_t stageBase) {
        const int k0 = c * 32;
        const __half *A, *B;
        int lda, kk;
        if (k0 < ISZ) { A = g_x16; lda = ISZ; kk = k0;        B = Bx; }
        else          { A = g_h16; lda = HSZ; kk = k0 - ISZ;  B = Bh; }
        CP16(stageBase + aSoff,
             A + (size_t)(rowBase + aRow) * lda + kk + aKc * 8);
        CP16(stageBase + A_BYTES + bSoff0,
             B + (size_t)(kk + bRow0) * HSZ + colBase + bNc0 * 8);
        CP16(stageBase + A_BYTES + bSoff1,
             B + (size_t)(kk + bRow1) * HSZ + colBase + bNc1 * 8);
        CP_COMMIT();
    };

    auto compute_chunk_s = [&](uint32_t stageBase) {
        const uint32_t sA = stageBase;
        const uint32_t sB = stageBase + A_BYTES;
#pragma unroll
        for (int ks = 0; ks < 2; ks++) {
            const int k = ks * 16;
            const uint32_t aoff =
                (uint32_t)(wm + (lane & 15)) * A_RSTRIDE +
                (uint32_t)(k + ((lane >> 4) << 3)) * 2;
            uint32_t af[2][4];
#pragma unroll
            for (int mi = 0; mi < 2; mi++) {
                const uint32_t d = aoff + mi * 16 * A_RSTRIDE;
                LDMATRIX_X4(af[mi][0], af[mi][1], af[mi][2], af[mi][3], sA + d);
            }
            uint32_t bf[2][4];
            const int l8 = lane & 7, t8 = lane >> 3;
#pragma unroll
            for (int np = 0; np < 2; np++) {
                const uint32_t d =
                    (uint32_t)(k + (t8 & 1) * 8 + l8) * BT_RSTRIDE +
                    (uint32_t)(wn + np * 16 + (t8 >> 1) * 8) * 2;
                LDMATRIX_X4_T(bf[np][0], bf[np][1], bf[np][2], bf[np][3], sB + d);
            }
#pragma unroll
            for (int mi = 0; mi < 2; mi++)
#pragma unroll
                for (int ni = 0; ni < 4; ni++) {
                    const int np = ni >> 1, q = (ni & 1) * 2;
                    MMA16816(acc[mi][ni], af[mi], bf[np][q], bf[np][q + 1]);
                }
        }
    };

    load_chunk_s(0, sb + 0 * STAGE_BYTES);
    load_chunk_s(1, sb + 1 * STAGE_BYTES);
    load_chunk_s(2, sb + 2 * STAGE_BYTES);
    load_chunk_s(3, sb + 3 * STAGE_BYTES);

    int c = 0;
    // steady state, unrolled by NSTAGE: c%5 == u (c advances by 5 from 0)
    for (; c + 8 < nchunks; c += NSTAGE) {
#pragma unroll
        for (int u = 0; u < NSTAGE; u++) {
            CP_WAITN(3);
            __syncthreads();
            load_chunk_s(c + u + 4, sb + ((u + 4) % NSTAGE) * STAGE_BYTES);
            compute_chunk_s(sb + u * STAGE_BYTES);
        }
    }
    // remainder (generic stage indexing, tapered waits)
    for (; c < nchunks; c++) {
        PIPE_WAIT_TAIL(c, nchunks);
        __syncthreads();
        if (c + 4 < nchunks)
            load_chunk_s(c + 4, sb + ((c + 4) % NSTAGE) * STAGE_BYTES);
        compute_chunk_s(sb + (c % NSTAGE) * STAGE_BYTES);
    }

    const float* bias = z ? b_h : b_g;
    float* out = z ? h_new : g_new;

#pragma unroll
    for (int mi = 0; mi < 2; mi++) {
#pragma unroll
        for (int ni = 0; ni < 4; ni++) {
            const int col = colBase + wn + ni * 8 + (lane & 3) * 2;
#pragma unroll
            for (int hf = 0; hf < 2; hf++) {
                const int row = rowBase + wm + mi * 16 + (lane >> 2) + hf * 8;
                const float c0 = acc[mi][ni][hf * 2 + 0];
                const float c1 = acc[mi][ni][hf * 2 + 1];
                const size_t oidx = (size_t)row * HSZ + col;
                const float t0 = tanhf(c0 + bias[col]);
                const float t1 = tanhf(c1 + bias[col + 1]);
                if (z == 0) {
                    float2 r; r.x = t0; r.y = t1;
                    *(float2*)&out[oidx] = r;
                } else {
                    const float2 gv = *(const float2*)&graw[oidx];
                    const float2 hv = *(const float2*)&hraw[oidx];
                    float2 hn;
                    hn.x = gv.x * t0 + (1.0f - gv.x) * hv.x;
                    hn.y = gv.y * t1 + (1.0f - gv.y) * hv.y;
                    *(float2*)&out[oidx] = hn;
                    *(__half2*)&g_hn16[oidx] =
                        __halves2half2(__float2half_rn(hn.x), __float2half_rn(hn.y));
                }
            }
        }
    }
}

// ---------------------------------------------------------------------------
// Output GEMM: o = h_new @ lin_w^T + lin_b (B is [N,K], non-trans path)
// ---------------------------------------------------------------------------
__global__ __launch_bounds__(NTH, 2) void gemm_out_kernel(
    const float* __restrict__ bias,
    float* __restrict__ out)
{
    extern __shared__ __align__(128) unsigned char dsm[];
    const uint32_t sb = smem_u32(dsm);
    const int tid = threadIdx.x;
    const int wid = tid >> 5, lane = tid & 31;
    const int rowBase = blockIdx.y * 64;
    const int colBase = blockIdx.x * 128;
    const int nchunks = HSZ / 32;   // 64

    const int wm = (wid >> 2) * 32;
    const int wn = (wid & 3) * 32;

    const int aRow = tid >> 2, aKc = tid & 3;
    const uint32_t aSoff = (uint32_t)aRow * A_RSTRIDE + aKc * 16;
    const int bRow0 = (tid * 2) >> 2, bKc0 = (tid * 2) & 3;
    const int bRow1 = (tid * 2 + 1) >> 2, bKc1 = (tid * 2 + 1) & 3;
    const uint32_t bSoff0 = (uint32_t)bRow0 * A_RSTRIDE + bKc0 * 16;
    const uint32_t bSoff1 = (uint32_t)bRow1 * A_RSTRIDE + bKc1 * 16;

    float acc[2][4][4];
#pragma unroll
    for (int mi = 0; mi < 2; mi++)
#pragma unroll
        for (int ni = 0; ni < 4; ni++)
#pragma unroll
            for (int q = 0; q < 4; q++) acc[mi][ni][q] = 0.0f;

    auto load_chunk_s = [&](int c, uint32_t stageBase) {
        const int kk = c * 32;
        CP16(stageBase + aSoff,
             g_hn16 + (size_t)(rowBase + aRow) * HSZ + kk + aKc * 8);
        CP16(stageBase + A_BYTES + bSoff0,
             g_linw + (size_t)(colBase + bRow0) * HSZ + kk + bKc0 * 8);
        CP16(stageBase + A_BYTES + bSoff1,
             g_linw + (size_t)(colBase + bRow1) * HSZ + kk + bKc1 * 8);
        CP_COMMIT();
    };

    auto compute_chunk_s = [&](uint32_t stageBase) {
        const uint32_t sA = stageBase;
        const uint32_t sB = stageBase + A_BYTES;
#pragma unroll
        for (int ks = 0; ks < 2; ks++) {
            const int k = ks * 16;
            const uint32_t aoff =
                (uint32_t)(wm + (lane & 15)) * A_RSTRIDE +
                (uint32_t)(k + ((lane >> 4) << 3)) * 2;
            uint32_t af[2][4];
#pragma unroll
            for (int mi = 0; mi < 2; mi++) {
                const uint32_t d = aoff + mi * 16 * A_RSTRIDE;
                LDMATRIX_X4(af[mi][0], af[mi][1], af[mi][2], af[mi][3], sA + d);
            }
            const uint32_t boff =
                (uint32_t)(wn + ((lane >> 4) << 3) + (lane & 7)) * A_RSTRIDE +
                (uint32_t)(k + (((lane >> 3) & 1) << 3)) * 2;
            uint32_t bf[2][4];
#pragma unroll
            for (int np = 0; np < 2; np++) {
                const uint32_t d = boff + np * 16 * A_RSTRIDE;
                LDMATRIX_X4(bf[np][0], bf[np][1], bf[np][2], bf[np][3], sB + d);
            }
#pragma unroll
            for (int mi = 0; mi < 2; mi++)
#pragma unroll
                for (int ni = 0; ni < 4; ni++) {
                    const int np = ni >> 1, q = (ni & 1) * 2;
                    MMA16816(acc[mi][ni], af[mi], bf[np][q], bf[np][q + 1]);
                }
        }
    };

    load_chunk_s(0, sb + 0 * STAGE_BYTES);
    load_chunk_s(1, sb + 1 * STAGE_BYTES);
    load_chunk_s(2, sb + 2 * STAGE_BYTES);
    load_chunk_s(3, sb + 3 * STAGE_BYTES);

    int c = 0;
    for (; c + 8 < nchunks; c += NSTAGE) {
#pragma unroll
        for (int u = 0; u < NSTAGE; u++) {
            CP_WAITN(3);
            __syncthreads();
            load_chunk_s(c + u + 4, sb + ((u + 4) % NSTAGE) * STAGE_BYTES);
            compute_chunk_s(sb + u * STAGE_BYTES);
        }
    }
    for (; c < nchunks; c++) {
        PIPE_WAIT_TAIL(c, nchunks);
        __syncthreads();
        if (c + 4 < nchunks)
            load_chunk_s(c + 4, sb + ((c + 4) % NSTAGE) * STAGE_BYTES);
        compute_chunk_s(sb + (c % NSTAGE) * STAGE_BYTES);
    }

#pragma unroll
    for (int mi = 0; mi < 2; mi++) {
#pragma unroll
        for (int ni = 0; ni < 4; ni++) {
            const int col = colBase + wn + ni * 8 + (lane & 3) * 2;
#pragma unroll
            for (int hf = 0; hf < 2; hf++) {
                const int row = rowBase + wm + mi * 16 + (lane >> 2) + hf * 8;
                float2 r;
                r.x = acc[mi][ni][hf * 2 + 0] + bias[col];
                r.y = acc[mi][ni][hf * 2 + 1] + bias[col + 1];
                *(float2*)&out[(size_t)row * ISZ + col] = r;
            }
        }
    }
}

// ---------------------------------------------------------------------------
// Launch
// ---------------------------------------------------------------------------
extern "C" void kernel_launch(void* const* d_in, const int* in_sizes, int n_in,
                              void* d_out, int out_size) {
    const float* x     = (const float*)d_in[0];
    const float* h     = (const float*)d_in[1];
    const float* g     = (const float*)d_in[2];
    const float* w_xh  = (const float*)d_in[3];
    const float* w_hh  = (const float*)d_in[4];
    const float* b_h   = (const float*)d_in[5];
    const float* w_gx  = (const float*)d_in[6];
    const float* w_gh  = (const float*)d_in[7];
    const float* b_g   = (const float*)d_in[8];
    const float* lin_w = (const float*)d_in[9];
    const float* lin_b = (const float*)d_in[10];

    float* o     = (float*)d_out;
    float* h_new = o + (size_t)BSZ * ISZ;
    float* g_new = h_new + (size_t)BSZ * HSZ;

    void *x16, *h16, *lw, *gx, *gh, *xh, *hh;
    cudaGetSymbolAddress(&x16, g_x16);
    cudaGetSymbolAddress(&h16, g_h16);
    cudaGetSymbolAddress(&lw, g_linw);
    cudaGetSymbolAddress(&gx, g_wgx);
    cudaGetSymbolAddress(&gh, g_wgh);
    cudaGetSymbolAddress(&xh, g_wxh);
    cudaGetSymbolAddress(&hh, g_whh);

    cudaFuncSetAttribute(gemm_gates_kernel, cudaFuncAttributeMaxDynamicSharedMemorySize, SMEM_MAIN);
    cudaFuncSetAttribute(gemm_out_kernel,   cudaFuncAttributeMaxDynamicSharedMemorySize, SMEM_MAIN);

    // single fused fp32 -> fp16 convert (MLP=4, streaming stores)
    ConvSegs segs;
    segs.src[0] = (const float4*)x;     segs.dst[0] = (__half2*)x16; segs.n4[0] = BSZ * ISZ / 4;
    segs.src[1] = (const float4*)h;     segs.dst[1] = (__half2*)h16; segs.n4[1] = BSZ * HSZ / 4;
    segs.src[2] = (const float4*)lin_w; segs.dst[2] = (__half2*)lw;  segs.n4[2] = ISZ * HSZ / 4;
    segs.src[3] = (const float4*)w_gx;  segs.dst[3] = (__half2*)gx;  segs.n4[3] = ISZ * HSZ / 4;
    segs.src[4] = (const float4*)w_gh;  segs.dst[4] = (__half2*)gh;  segs.n4[4] = HSZ * HSZ / 4;
    segs.src[5] = (const float4*)w_xh;  segs.dst[5] = (__half2*)xh;  segs.n4[5] = ISZ * HSZ / 4;
    segs.src[6] = (const float4*)w_hh;  segs.dst[6] = (__half2*)hh;  segs.n4[6] = HSZ * HSZ / 4;
    int total4 = 0;
    for (int t = 0; t < NSEG; t++) total4 += segs.n4[t];
    const int conv_blocks = (total4 + 256 * CONV_PER_THREAD - 1) / (256 * CONV_PER_THREAD);
    conv_all_kernel<<<conv_blocks, 256>>>(segs);

    // merged gate GEMMs (z=0: g_new, z=1: h_new)
    gemm_gates_kernel<<<dim3(HSZ / 128, BSZ / 64, 2), NTH, SMEM_MAIN>>>(
        b_g, b_h, g, h, g_new, h_new);

    // output GEMM
    gemm_out_kernel<<<dim3(ISZ / 128, BSZ / 64), NTH, SMEM_MAIN>>>(lin_b, o);
}